// round 2
// baseline (speedup 1.0000x reference)
#include <cuda_runtime.h>

#define NB    1024
#define NJ    24
#define NV    6890
#define NBETA 10
#define PB    207
#define NQ    218          // 1 + 10 + 207
#define JJT   576          // 24*24
#define CCN   1728         // JJT*3

#define PP_LD   704        // padded N of pack matrix (>= NQ*3 = 654), /4 ok
#define PP_ROWS 6912       // padded K (>= NV), multiple of 16
#define GT_LD   6912       // padded K for G^T, 16B-aligned rows
#define X_LD    224        // padded K for X (>= 218), multiple of 16
#define CCR_ROWS 224

__device__ __align__(16) float g_Pp[PP_ROWS * PP_LD];     // [v][q*3+c]
__device__ __align__(16) float g_Gt[JJT * GT_LD];          // [j*24+jt][v]
__device__ __align__(16) float g_CCr[CCR_ROWS * CCN];      // [q][(j*24+jt)*3+c]
__device__ __align__(16) float g_X[NB * X_LD];             // [b][q]
__device__ __align__(16) float g_Rs[NB * NJ * 9];
__device__ __align__(16) float g_A[NB * NJ * 12];          // [b][jt][c*4+k]
__device__ __align__(16) float g_M[NB * CCN];
__device__ float g_W2[JJT];
__device__ float g_JS[NBETA * NJ * 3];
__device__ float g_J0[NJ * 3];

__constant__ int c_par[NJ] = {-1,0,0,0,1,2,3,4,5,6,7,8,9,9,9,12,13,14,16,17,18,19,20,21};

// ---------------------------------------------------------------------------
// Pack P (v_template / shapedirs / posedirs) into K-major [v][q*3+c], zero-pad.
__global__ void k_pack(const float* __restrict__ vt, const float* __restrict__ sd,
                       const float* __restrict__ pd) {
    int t = blockIdx.x * blockDim.x + threadIdx.x;
    int v = t % PP_ROWS;
    int q = t / PP_ROWS;
    if (q >= 235) return;   // 235*3 covers PP_LD
    float a0 = 0.f, a1 = 0.f, a2 = 0.f;
    if (q < NQ && v < NV) {
        const float* src;
        size_t row;
        if (q == 0)           { src = vt; row = 0; }
        else if (q <= NBETA)  { src = sd; row = (size_t)(q - 1); }
        else                  { src = pd; row = (size_t)(q - 11); }
        const float* p = src + row * (size_t)(NV * 3) + 3 * v;
        a0 = p[0]; a1 = p[1]; a2 = p[2];
    }
    int col = q * 3;
    float* dst = g_Pp + (size_t)v * PP_LD;
    if (col + 0 < PP_LD) dst[col + 0] = a0;
    if (col + 1 < PP_LD) dst[col + 1] = a1;
    if (col + 2 < PP_LD) dst[col + 2] = a2;
}

// ---------------------------------------------------------------------------
// G^T[jjt][v] = Jr[v,j] * w[v,jt], zero-padded in v.
__global__ void k_G(const float* __restrict__ Jr, const float* __restrict__ w) {
    int v = blockIdx.x * blockDim.x + threadIdx.x;
    if (v >= GT_LD) return;
    if (v < NV) {
        float jr[NJ], ww[NJ];
#pragma unroll
        for (int j = 0; j < NJ; j++) { jr[j] = Jr[v * NJ + j]; ww[j] = w[v * NJ + j]; }
#pragma unroll
        for (int j = 0; j < NJ; j++)
#pragma unroll
            for (int jt = 0; jt < NJ; jt++)
                g_Gt[(size_t)(j * NJ + jt) * GT_LD + v] = jr[j] * ww[jt];
    } else {
        for (int e = 0; e < JJT; e++) g_Gt[(size_t)e * GT_LD + v] = 0.f;
    }
}

// ---------------------------------------------------------------------------
// W2[jjt] = sum_v G^T[jjt][v]
__global__ void k_W2() {
    __shared__ float s[256];
    int m = blockIdx.x;
    float acc = 0.f;
    for (int v = threadIdx.x; v < GT_LD; v += 256) acc += g_Gt[(size_t)m * GT_LD + v];
    s[threadIdx.x] = acc; __syncthreads();
    for (int o = 128; o > 0; o >>= 1) {
        if (threadIdx.x < o) s[threadIdx.x] += s[threadIdx.x + o];
        __syncthreads();
    }
    if (threadIdx.x == 0) g_W2[m] = s[0];
}

// ---------------------------------------------------------------------------
// JS[s,j,c] = sum_v Jr[v,j]*shapedirs[s,3v+c];  J0 via v_template.
__global__ void k_JS(const float* __restrict__ Jr, const float* __restrict__ sd,
                     const float* __restrict__ vt) {
    __shared__ float s[256];
    int o = blockIdx.x;                 // 0..791  (720 JS + 72 J0)
    int isJ0 = (o >= 720);
    int rr = isJ0 ? (o - 720) : (o % 72);
    int srow = isJ0 ? 0 : (o / 72);
    int j = rr / 3, c = rr % 3;
    const float* src = isJ0 ? vt : (sd + (size_t)srow * (NV * 3));
    float acc = 0.f;
    for (int v = threadIdx.x; v < NV; v += 256)
        acc += Jr[v * NJ + j] * src[3 * v + c];
    s[threadIdx.x] = acc; __syncthreads();
    for (int w = 128; w > 0; w >>= 1) {
        if (threadIdx.x < w) s[threadIdx.x] += s[threadIdx.x + w];
        __syncthreads();
    }
    if (threadIdx.x == 0) { if (isJ0) g_J0[rr] = s[0]; else g_JS[o] = s[0]; }
}

// ---------------------------------------------------------------------------
// Rodrigues per (b, joint); also assemble X = [1, beta, pose_feature].
__global__ void k_rod(const float* __restrict__ theta, const float* __restrict__ beta) {
    int t = blockIdx.x * blockDim.x + threadIdx.x;
    if (t >= NB * NJ) return;
    int b = t / NJ, i = t % NJ;
    const float* th = theta + b * 72 + i * 3;
    float tx = th[0], ty = th[1], tz = th[2];
    float ax = tx + 1e-8f, ay = ty + 1e-8f, az = tz + 1e-8f;
    float angle = sqrtf(ax * ax + ay * ay + az * az);
    float inv = 1.0f / angle;
    float nx = tx * inv, ny = ty * inv, nz = tz * inv;
    float h = 0.5f * angle;
    float qw = cosf(h), sh = sinf(h);
    float qx = sh * nx, qy = sh * ny, qz = sh * nz;
    float qn = rsqrtf(qw * qw + qx * qx + qy * qy + qz * qz);
    qw *= qn; qx *= qn; qy *= qn; qz *= qn;
    float R[9];
    R[0] = qw*qw + qx*qx - qy*qy - qz*qz; R[1] = 2.f*(qx*qy - qw*qz); R[2] = 2.f*(qx*qz + qw*qy);
    R[3] = 2.f*(qx*qy + qw*qz); R[4] = qw*qw - qx*qx + qy*qy - qz*qz; R[5] = 2.f*(qy*qz - qw*qx);
    R[6] = 2.f*(qx*qz - qw*qy); R[7] = 2.f*(qy*qz + qw*qx); R[8] = qw*qw - qx*qx - qy*qy + qz*qz;
    float* rs = g_Rs + (size_t)t * 9;
#pragma unroll
    for (int r = 0; r < 9; r++) rs[r] = R[r];
    if (i > 0) {
        float* x = g_X + (size_t)b * X_LD + 11 + (i - 1) * 9;
#pragma unroll
        for (int r = 0; r < 9; r++)
            x[r] = R[r] - ((r == 0 || r == 4 || r == 8) ? 1.f : 0.f);
    } else {
        float* x = g_X + (size_t)b * X_LD;
        x[0] = 1.f;
#pragma unroll
        for (int s = 0; s < NBETA; s++) x[1 + s] = beta[b * NBETA + s];
#pragma unroll
        for (int p = NQ; p < X_LD; p++) x[p] = 0.f;
    }
}

// ---------------------------------------------------------------------------
// Kinematic chain: one warp per batch; builds A[b][jt][c*4+k].
__global__ void k_chain(const float* __restrict__ beta) {
    __shared__ float sJ[8][72];
    __shared__ float sR[8][216];
    __shared__ float sT[8][72];
    int w = threadIdx.x >> 5, lane = threadIdx.x & 31;
    int b = blockIdx.x * 8 + w;
    for (int e = lane; e < 72; e += 32) {
        float val = g_J0[e];
#pragma unroll
        for (int s = 0; s < NBETA; s++) val += beta[b * NBETA + s] * g_JS[s * 72 + e];
        sJ[w][e] = val;
    }
    __syncwarp();
    if (lane == 0) {
        const float* R0 = g_Rs + (size_t)(b * NJ) * 9;
        for (int r = 0; r < 9; r++) sR[w][r] = R0[r];
        for (int c = 0; c < 3; c++) sT[w][c] = sJ[w][c];
        for (int i = 1; i < NJ; i++) {
            int p = c_par[i];
            const float* Rl = g_Rs + (size_t)(b * NJ + i) * 9;
            float tl[3];
            for (int c = 0; c < 3; c++) tl[c] = sJ[w][i * 3 + c] - sJ[w][p * 3 + c];
            for (int r = 0; r < 3; r++) {
                for (int c = 0; c < 3; c++) {
                    float acc = 0.f;
                    for (int m = 0; m < 3; m++) acc += sR[w][p * 9 + r * 3 + m] * Rl[m * 3 + c];
                    sR[w][i * 9 + r * 3 + c] = acc;
                }
                float ta = sT[w][p * 3 + r];
                for (int m = 0; m < 3; m++) ta += sR[w][p * 9 + r * 3 + m] * tl[m];
                sT[w][i * 3 + r] = ta;
            }
        }
    }
    __syncwarp();
    for (int e = lane; e < 288; e += 32) {
        int jt = e / 12, r = e % 12, c = r >> 2, k = r & 3;
        float val;
        if (k < 3) val = sR[w][jt * 9 + c * 3 + k];
        else {
            val = sT[w][jt * 3 + c];
            for (int m = 0; m < 3; m++) val -= sR[w][jt * 9 + c * 3 + m] * sJ[w][jt * 3 + m];
        }
        g_A[(size_t)b * 288 + e] = val;
    }
}

// ---------------------------------------------------------------------------
// GEMM1: CC^T[jjt(576), qc(654 in 704)] = G^T[576,6912] @ Pp[6912,704]
// split-K=3, atomicAdd scatter into CCr[q][(jjt)*3+c].
__global__ void k_gemm_cc() {
    __shared__ float As[16][68];
    __shared__ float Bs[16][64];
    int t = threadIdx.x;
    int m0 = blockIdx.y * 64, n0 = blockIdx.x * 64;
    int kbeg = blockIdx.z * 2304, kend = kbeg + 2304;
    int a_m = t >> 2, a_k = (t & 3) * 4;
    int b_k = t >> 4, b_n = (t & 15) * 4;
    int ty = t >> 4, tx = t & 15;
    float acc[4][4];
#pragma unroll
    for (int i = 0; i < 4; i++)
#pragma unroll
        for (int j = 0; j < 4; j++) acc[i][j] = 0.f;

    for (int kk = kbeg; kk < kend; kk += 16) {
        float4 av = *(const float4*)&g_Gt[(size_t)(m0 + a_m) * GT_LD + kk + a_k];
        As[a_k + 0][a_m] = av.x; As[a_k + 1][a_m] = av.y;
        As[a_k + 2][a_m] = av.z; As[a_k + 3][a_m] = av.w;
        float4 bv = *(const float4*)&g_Pp[(size_t)(kk + b_k) * PP_LD + n0 + b_n];
        *(float4*)&Bs[b_k][b_n] = bv;
        __syncthreads();
#pragma unroll
        for (int k = 0; k < 16; k++) {
            float4 a = *(const float4*)&As[k][ty * 4];
            float4 bb = *(const float4*)&Bs[k][tx * 4];
            float ar[4] = {a.x, a.y, a.z, a.w};
            float br[4] = {bb.x, bb.y, bb.z, bb.w};
#pragma unroll
            for (int i = 0; i < 4; i++)
#pragma unroll
                for (int j = 0; j < 4; j++) acc[i][j] += ar[i] * br[j];
        }
        __syncthreads();
    }
#pragma unroll
    for (int i = 0; i < 4; i++) {
        int m = m0 + ty * 4 + i;
#pragma unroll
        for (int j = 0; j < 4; j++) {
            int n = n0 + tx * 4 + j;
            if (n < NQ * 3) {
                int q = n / 3, c = n - q * 3;
                atomicAdd(&g_CCr[(size_t)q * CCN + m * 3 + c], acc[i][j]);
            }
        }
    }
}

// ---------------------------------------------------------------------------
// GEMM2: M[1024, 1728] = X[1024, 224] @ CCr[224, 1728]
__global__ void k_gemm_m() {
    __shared__ float As[16][68];
    __shared__ float Bs[16][64];
    int t = threadIdx.x;
    int m0 = blockIdx.y * 64, n0 = blockIdx.x * 64;
    int a_m = t >> 2, a_k = (t & 3) * 4;
    int b_k = t >> 4, b_n = (t & 15) * 4;
    int ty = t >> 4, tx = t & 15;
    float acc[4][4];
#pragma unroll
    for (int i = 0; i < 4; i++)
#pragma unroll
        for (int j = 0; j < 4; j++) acc[i][j] = 0.f;

    for (int kk = 0; kk < X_LD; kk += 16) {
        float4 av = *(const float4*)&g_X[(size_t)(m0 + a_m) * X_LD + kk + a_k];
        As[a_k + 0][a_m] = av.x; As[a_k + 1][a_m] = av.y;
        As[a_k + 2][a_m] = av.z; As[a_k + 3][a_m] = av.w;
        float4 bv = *(const float4*)&g_CCr[(size_t)(kk + b_k) * CCN + n0 + b_n];
        *(float4*)&Bs[b_k][b_n] = bv;
        __syncthreads();
#pragma unroll
        for (int k = 0; k < 16; k++) {
            float4 a = *(const float4*)&As[k][ty * 4];
            float4 bb = *(const float4*)&Bs[k][tx * 4];
            float ar[4] = {a.x, a.y, a.z, a.w};
            float br[4] = {bb.x, bb.y, bb.z, bb.w};
#pragma unroll
            for (int i = 0; i < 4; i++)
#pragma unroll
                for (int j = 0; j < 4; j++) acc[i][j] += ar[i] * br[j];
        }
        __syncthreads();
    }
#pragma unroll
    for (int i = 0; i < 4; i++) {
        int m = m0 + ty * 4 + i;
        float4 o = make_float4(acc[i][0], acc[i][1], acc[i][2], acc[i][3]);
        *(float4*)&g_M[(size_t)m * CCN + n0 + tx * 4] = o;
    }
}

// ---------------------------------------------------------------------------
// Final: joints[b,j,c] = sum_jt ( A[b,jt,c,:3].M[b,j,jt,:] + A[b,jt,c,3]*W2[j,jt] )
__global__ void k_final(float* __restrict__ out) {
    __shared__ float sM[CCN];
    __shared__ float sA[288];
    __shared__ float sW[JJT];
    int b = blockIdx.x, t = threadIdx.x;
    for (int e = t; e < CCN; e += 128) sM[e] = g_M[(size_t)b * CCN + e];
    for (int e = t; e < 288; e += 128) sA[e] = g_A[(size_t)b * 288 + e];
    for (int e = t; e < JJT; e += 128) sW[e] = g_W2[e];
    __syncthreads();
    if (t < 72) {
        int j = t / 3, c = t % 3;
        float s = 0.f;
#pragma unroll
        for (int jt = 0; jt < NJ; jt++) {
            const float* a = &sA[jt * 12 + c * 4];
            const float* m = &sM[(j * NJ + jt) * 3];
            s += a[0] * m[0] + a[1] * m[1] + a[2] * m[2] + a[3] * sW[j * NJ + jt];
        }
        out[b * 72 + t] = s;
    }
}

// ---------------------------------------------------------------------------
extern "C" void kernel_launch(void* const* d_in, const int* in_sizes, int n_in,
                              void* d_out, int out_size) {
    const float* beta  = (const float*)d_in[0];
    const float* theta = (const float*)d_in[1];
    const float* vt    = (const float*)d_in[2];
    const float* sd    = (const float*)d_in[3];
    const float* pd    = (const float*)d_in[4];
    const float* Jr    = (const float*)d_in[5];
    const float* wts   = (const float*)d_in[6];
    float* out = (float*)d_out;

    void* ccr_ptr = 0;
    cudaGetSymbolAddress(&ccr_ptr, g_CCr);
    cudaMemsetAsync(ccr_ptr, 0, sizeof(float) * CCR_ROWS * CCN);

    k_pack<<<(235 * PP_ROWS + 255) / 256, 256>>>(vt, sd, pd);
    k_G<<<GT_LD / 256, 256>>>(Jr, wts);
    k_W2<<<JJT, 256>>>();
    k_JS<<<792, 256>>>(Jr, sd, vt);
    k_rod<<<(NB * NJ + 255) / 256, 256>>>(theta, beta);
    k_chain<<<NB / 8, 256>>>(beta);
    k_gemm_cc<<<dim3(11, 9, 3), 256>>>();
    k_gemm_m<<<dim3(27, 16), 256>>>();
    k_final<<<NB, 128>>>(out);
}